// round 13
// baseline (speedup 1.0000x reference)
#include <cuda_runtime.h>
#include <cuda_bf16.h>
#include <cstdint>

#define BATCH 4
#define NPTS  8192
#define SPTS  2048
#define D1    128
#define D2    256
#define CIN   384
#define CMID  256
#define COUT  256
#define PTOT  (BATCH*NPTS)   // 32768

#define TM 128
#define TN 128
#define KC 32              // K chunk (bf16 elems)
#define ROWB 80            // 64B data + 16B pad -> conflict-free ldmatrix
#define TILEB (128*ROWB)   // 10240
#define OFF_AH 0
#define OFF_AL 10240
#define OFF_BH 20480
#define OFF_BL 30720
#define STAGEB 40960
#define SMEM_DYN (2*STAGEB)   // 81920; epilogue tile (67584B) reuses it

// ---------------- device scratch ----------------
__device__ float          g_f2t[BATCH*SPTS*D2];
__device__ __nv_bfloat16  g_Fh[(size_t)PTOT*CIN];
__device__ __nv_bfloat16  g_Fl[(size_t)PTOT*CIN];
__device__ float          g_y1[(size_t)PTOT*CMID];
__device__ float          g_y2[(size_t)PTOT*COUT];
__device__ __nv_bfloat16  g_B1h[(size_t)PTOT*CMID];
__device__ __nv_bfloat16  g_B1l[(size_t)PTOT*CMID];
__device__ __nv_bfloat16  g_W1h[CMID*CIN],  g_W1l[CMID*CIN];
__device__ __nv_bfloat16  g_W2h[COUT*CMID], g_W2l[COUT*CMID];
__device__ int            g_idx[PTOT*3];
__device__ float          g_w[PTOT*3];
__device__ float          g_s1[CMID], g_ss1[CMID], g_s2[COUT], g_ss2[COUT];
__device__ float          g_bnA1[CMID], g_bnB1[CMID], g_bnA2[COUT], g_bnB2[COUT];

// ---------------- asm helpers ----------------
static __device__ __forceinline__ uint32_t smem_u32(const void* p) {
    uint32_t a;
    asm("{ .reg .u64 t; cvta.to.shared.u64 t, %1; cvt.u32.u64 %0, t; }" : "=r"(a) : "l"(p));
    return a;
}
static __device__ __forceinline__ void mma16816(float* d, const uint32_t* a,
                                                uint32_t b0, uint32_t b1) {
    asm volatile(
        "mma.sync.aligned.m16n8k16.row.col.f32.bf16.bf16.f32 "
        "{%0,%1,%2,%3}, {%4,%5,%6,%7}, {%8,%9}, {%0,%1,%2,%3};"
        : "+f"(d[0]), "+f"(d[1]), "+f"(d[2]), "+f"(d[3])
        : "r"(a[0]), "r"(a[1]), "r"(a[2]), "r"(a[3]), "r"(b0), "r"(b1));
}
#define LDM4(r0, r1, r2, r3, addr) \
    asm volatile("ldmatrix.sync.aligned.m8n8.x4.shared.b16 {%0,%1,%2,%3}, [%4];" \
        : "=r"(r0), "=r"(r1), "=r"(r2), "=r"(r3) : "r"(addr))
#define CPA(dst, src) \
    asm volatile("cp.async.cg.shared.global [%0], [%1], 16;" :: "r"(dst), "l"(src))
#define CPA_COMMIT() asm volatile("cp.async.commit_group;")
#define CPA_WAIT1()  asm volatile("cp.async.wait_group 1;" ::: "memory")
#define CPA_WAIT0()  asm volatile("cp.async.wait_group 0;" ::: "memory")

static __device__ __forceinline__ uint32_t pack2(float a, float b) {
    return (uint32_t)__bfloat16_as_ushort(__float2bfloat16(a)) |
           ((uint32_t)__bfloat16_as_ushort(__float2bfloat16(b)) << 16);
}

// ---------------- prep ----------------
__global__ void prep_kernel(const float* __restrict__ W1, const float* __restrict__ W2) {
    int i = blockIdx.x * 256 + threadIdx.x;
    if (i < CMID * CIN) {
        float w = W1[i];
        __nv_bfloat16 h = __float2bfloat16(w);
        g_W1h[i] = h;
        g_W1l[i] = __float2bfloat16(w - __bfloat162float(h));
    }
    if (i < COUT * CMID) {
        float w = W2[i];
        __nv_bfloat16 h = __float2bfloat16(w);
        g_W2h[i] = h;
        g_W2l[i] = __float2bfloat16(w - __bfloat162float(h));
    }
    if (i < 256) { g_s1[i] = 0.f; g_ss1[i] = 0.f; g_s2[i] = 0.f; g_ss2[i] = 0.f; }
}

// ---------------- transpose feature2 ----------------
__global__ void transpose_f2_kernel(const float* __restrict__ f2) {
    __shared__ float tile[32][33];
    int b  = blockIdx.z;
    int s0 = blockIdx.x * 32, d0 = blockIdx.y * 32;
    const float* src = f2 + (size_t)b * D2 * SPTS;
    #pragma unroll
    for (int i = 0; i < 32; i += 8)
        tile[threadIdx.y + i][threadIdx.x] =
            src[(size_t)(d0 + threadIdx.y + i) * SPTS + s0 + threadIdx.x];
    __syncthreads();
    float* dst = g_f2t + (size_t)b * SPTS * D2;
    #pragma unroll
    for (int i = 0; i < 32; i += 8)
        dst[(size_t)(s0 + threadIdx.y + i) * D2 + d0 + threadIdx.x] =
            tile[threadIdx.x][threadIdx.y + i];
}

// ---------------- copy feature1 -> feat cols [256,384) ----------------
__global__ void copy_f1_kernel(const float* __restrict__ f1) {
    __shared__ float tile[32][33];
    int b  = blockIdx.z;
    int n0 = blockIdx.x * 32, d0 = blockIdx.y * 32;
    const float* src = f1 + (size_t)b * D1 * NPTS;
    #pragma unroll
    for (int i = 0; i < 32; i += 8)
        tile[threadIdx.y + i][threadIdx.x] =
            src[(size_t)(d0 + threadIdx.y + i) * NPTS + n0 + threadIdx.x];
    __syncthreads();
    #pragma unroll
    for (int i = 0; i < 32; i += 8) {
        float v = tile[threadIdx.x][threadIdx.y + i];
        size_t o = (size_t)(b * NPTS + n0 + threadIdx.y + i) * CIN + D2 + d0 + threadIdx.x;
        __nv_bfloat16 h = __float2bfloat16(v);
        g_Fh[o] = h;
        g_Fl[o] = __float2bfloat16(v - __bfloat162float(h));
    }
}

// ---------------- 3-NN: float4 candidate layout, 1 LDS.128/iter -----------
__global__ void __launch_bounds__(256) knn_kernel(const float* __restrict__ pos1,
                                                  const float* __restrict__ pos2) {
    __shared__ float4 sp[SPTS];     // 32 KB
    int b = blockIdx.y;
    const float* p2 = pos2 + (size_t)b * 3 * SPTS;
    for (int i = threadIdx.x; i < SPTS; i += blockDim.x) {
        float x = p2[i], y = p2[SPTS + i], z = p2[2 * SPTS + i];
        sp[i] = make_float4(x, y, z, x * x + y * y + z * z);
    }
    __syncthreads();
    int n = blockIdx.x * blockDim.x + threadIdx.x;
    const float* p1 = pos1 + (size_t)b * 3 * NPTS;
    float x = p1[n], y = p1[NPTS + n], z = p1[2 * NPTS + n];
    float sq1 = x * x + y * y + z * z;
    float b0 = 3.4e38f, b1 = 3.4e38f, b2 = 3.4e38f;
    int   i0 = 0, i1 = 0, i2 = 0;
    #pragma unroll 4
    for (int s = 0; s < SPTS; s++) {
        float4 t = sp[s];
        float dot = x * t.x + y * t.y + z * t.z;
        float d   = sq1 - 2.0f * dot + t.w;
        if (d < b2) {
            if (d < b1) {
                if (d < b0) { b2 = b1; i2 = i1; b1 = b0; i1 = i0; b0 = d; i0 = s; }
                else        { b2 = b1; i2 = i1; b1 = d;  i1 = s; }
            } else          { b2 = d;  i2 = s; }
        }
    }
    float w0 = 1.0f / fmaxf(b0, 1e-10f);
    float w1 = 1.0f / fmaxf(b1, 1e-10f);
    float w2 = 1.0f / fmaxf(b2, 1e-10f);
    float ws = w0 + w1 + w2;
    int p = b * NPTS + n;
    g_w[p * 3 + 0] = w0 / ws;  g_w[p * 3 + 1] = w1 / ws;  g_w[p * 3 + 2] = w2 / ws;
    g_idx[p * 3 + 0] = i0;     g_idx[p * 3 + 1] = i1;     g_idx[p * 3 + 2] = i2;
}

// ---------------- interp: warp per point ----------------
__global__ void __launch_bounds__(256) interp_kernel() {
    int p = (blockIdx.x * 256 + threadIdx.x) >> 5;
    int l = threadIdx.x & 31;
    int b = p >> 13;
    int i0 = g_idx[p * 3 + 0], i1 = g_idx[p * 3 + 1], i2 = g_idx[p * 3 + 2];
    float w0 = g_w[p * 3 + 0], w1 = g_w[p * 3 + 1], w2 = g_w[p * 3 + 2];
    const float* r0 = g_f2t + (size_t)(b * SPTS + i0) * D2 + l * 8;
    const float* r1 = g_f2t + (size_t)(b * SPTS + i1) * D2 + l * 8;
    const float* r2 = g_f2t + (size_t)(b * SPTS + i2) * D2 + l * 8;
    float4 a0 = *(const float4*)r0,       a1 = *(const float4*)(r0 + 4);
    float4 c0 = *(const float4*)r1,       c1 = *(const float4*)(r1 + 4);
    float4 e0 = *(const float4*)r2,       e1 = *(const float4*)(r2 + 4);
    float v[8];
    v[0] = w0 * a0.x + w1 * c0.x + w2 * e0.x;
    v[1] = w0 * a0.y + w1 * c0.y + w2 * e0.y;
    v[2] = w0 * a0.z + w1 * c0.z + w2 * e0.z;
    v[3] = w0 * a0.w + w1 * c0.w + w2 * e0.w;
    v[4] = w0 * a1.x + w1 * c1.x + w2 * e1.x;
    v[5] = w0 * a1.y + w1 * c1.y + w2 * e1.y;
    v[6] = w0 * a1.z + w1 * c1.z + w2 * e1.z;
    v[7] = w0 * a1.w + w1 * c1.w + w2 * e1.w;
    uint4 hv, lv;
    float lo[8];
    #pragma unroll
    for (int i = 0; i < 8; i++)
        lo[i] = v[i] - __bfloat162float(__float2bfloat16(v[i]));
    hv.x = pack2(v[0], v[1]); hv.y = pack2(v[2], v[3]);
    hv.z = pack2(v[4], v[5]); hv.w = pack2(v[6], v[7]);
    lv.x = pack2(lo[0], lo[1]); lv.y = pack2(lo[2], lo[3]);
    lv.z = pack2(lo[4], lo[5]); lv.w = pack2(lo[6], lo[7]);
    size_t o = (size_t)p * CIN + l * 8;
    *(uint4*)(g_Fh + o) = hv;
    *(uint4*)(g_Fl + o) = lv;
}

// ---------------- convert y1 -> relu(bn1(y1)) bf16 hi/lo -------------------
__global__ void __launch_bounds__(256) convert1_kernel() {
    size_t i = (size_t)blockIdx.x * 256 + threadIdx.x;
    int c = (int)((i * 4) & 255);
    float4 v  = ((const float4*)g_y1)[i];
    float4 Ac = *(const float4*)&g_bnA1[c];
    float4 Bc = *(const float4*)&g_bnB1[c];
    float x0 = fmaxf(v.x * Ac.x + Bc.x, 0.f);
    float x1 = fmaxf(v.y * Ac.y + Bc.y, 0.f);
    float x2 = fmaxf(v.z * Ac.z + Bc.z, 0.f);
    float x3 = fmaxf(v.w * Ac.w + Bc.w, 0.f);
    uint2 hv, lv;
    hv.x = pack2(x0, x1); hv.y = pack2(x2, x3);
    lv.x = pack2(x0 - __bfloat162float(__float2bfloat16(x0)),
                 x1 - __bfloat162float(__float2bfloat16(x1)));
    lv.y = pack2(x2 - __bfloat162float(__float2bfloat16(x2)),
                 x3 - __bfloat162float(__float2bfloat16(x3)));
    ((uint2*)g_B1h)[i] = hv;
    ((uint2*)g_B1l)[i] = lv;
}

// ---------------- split-bf16 GEMM: double-buffered cp.async pipeline -------
// MODE 0: y1 = W1 @ feat^T + b1 (K=384, NC=12)
// MODE 1: y2 = W2 @ B1^T + b2   (K=256, NC=8)
template<int NC, int MODE>
__global__ void __launch_bounds__(256, 2) gemm_mma(const float* __restrict__ bias) {
    extern __shared__ __align__(16) char sm[];
    int tid = threadIdx.x;
    int w   = tid >> 5, l = tid & 31;
    int mw  = (w >> 2) * 64;
    int nw  = (w & 3) * 32;
    int m0  = blockIdx.y * TM;
    int p0  = blockIdx.x * TN;
    const int AK = NC * KC;

    const __nv_bfloat16* Ah_src = (MODE == 0) ? g_W1h : g_W2h;
    const __nv_bfloat16* Al_src = (MODE == 0) ? g_W1l : g_W2l;
    const __nv_bfloat16* Bh_src = (MODE == 0) ? g_Fh  : g_B1h;
    const __nv_bfloat16* Bl_src = (MODE == 0) ? g_Fl  : g_B1l;

    uint32_t smb = smem_u32(sm);
    // ldmatrix per-lane offsets (within a stage)
    uint32_t aoff = (uint32_t)(mw + (l & 15)) * ROWB + ((l >> 4) * 16);
    uint32_t boff = (uint32_t)(nw + (l & 7) + ((l >> 4) << 3)) * ROWB + (((l >> 3) & 1) * 16);
    // staging: thread -> row (tid>>1), seg pair ((tid&1)*2)
    int sr = tid >> 1, sc2 = (tid & 1) * 2;
    uint32_t stoff = (uint32_t)sr * ROWB + sc2 * 16;

    float acc[4][4][4] = {};

    // prologue: load chunk 0
    {
        uint32_t d = smb + stoff;
        size_t gA = (size_t)(m0 + sr) * AK + sc2 * 8;
        size_t gB = (size_t)(p0 + sr) * AK + sc2 * 8;
        CPA(d + OFF_AH, Ah_src + gA); CPA(d + OFF_AH + 16, Ah_src + gA + 8);
        CPA(d + OFF_AL, Al_src + gA); CPA(d + OFF_AL + 16, Al_src + gA + 8);
        CPA(d + OFF_BH, Bh_src + gB); CPA(d + OFF_BH + 16, Bh_src + gB + 8);
        CPA(d + OFF_BL, Bl_src + gB); CPA(d + OFF_BL + 16, Bl_src + gB + 8);
        CPA_COMMIT();
    }

    for (int c = 0; c < NC; ++c) {
        if (c + 1 < NC) {   // prefetch next chunk into other buffer
            int kc = (c + 1) * KC;
            uint32_t d = smb + ((c + 1) & 1) * STAGEB + stoff;
            size_t gA = (size_t)(m0 + sr) * AK + kc + sc2 * 8;
            size_t gB = (size_t)(p0 + sr) * AK + kc + sc2 * 8;
            CPA(d + OFF_AH, Ah_src + gA); CPA(d + OFF_AH + 16, Ah_src + gA + 8);
            CPA(d + OFF_AL, Al_src + gA); CPA(d + OFF_AL + 16, Al_src + gA + 8);
            CPA(d + OFF_BH, Bh_src + gB); CPA(d + OFF_BH + 16, Bh_src + gB + 8);
            CPA(d + OFF_BL, Bl_src + gB); CPA(d + OFF_BL + 16, Bl_src + gB + 8);
            CPA_COMMIT();
            CPA_WAIT1();
        } else {
            CPA_WAIT0();
        }
        __syncthreads();
        uint32_t base = smb + (c & 1) * STAGEB;
        #pragma unroll
        for (int kk = 0; kk < 2; kk++) {
            uint32_t ka = base + aoff + kk * 32;
            uint32_t kb = base + boff + kk * 32;
            uint32_t ah[4][4], al[4][4], bh[4][2], bl[4][2];
            #pragma unroll
            for (int mi = 0; mi < 4; mi++) {
                LDM4(ah[mi][0], ah[mi][1], ah[mi][2], ah[mi][3], ka + OFF_AH + mi * (16 * ROWB));
                LDM4(al[mi][0], al[mi][1], al[mi][2], al[mi][3], ka + OFF_AL + mi * (16 * ROWB));
            }
            LDM4(bh[0][0], bh[0][1], bh[1][0], bh[1][1], kb + OFF_BH);
            LDM4(bh[2][0], bh[2][1], bh[3][0], bh[3][1], kb + OFF_BH + 16 * ROWB);
            LDM4(bl[0][0], bl[0][1], bl[1][0], bl[1][1], kb + OFF_BL);
            LDM4(bl[2][0], bl[2][1], bl[3][0], bl[3][1], kb + OFF_BL + 16 * ROWB);
            #pragma unroll
            for (int ni = 0; ni < 4; ni++)
                #pragma unroll
                for (int mi = 0; mi < 4; mi++) {
                    mma16816(acc[mi][ni], ah[mi], bh[ni][0], bh[ni][1]);
                    mma16816(acc[mi][ni], ah[mi], bl[ni][0], bl[ni][1]);
                    mma16816(acc[mi][ni], al[mi], bh[ni][0], bh[ni][1]);
                }
        }
        __syncthreads();   // compute done before this buffer is overwritten
    }

    // --- epilogue ---
    float* tile = (float*)sm;
    #pragma unroll
    for (int mi = 0; mi < 4; mi++) {
        int c_ = mw + mi * 16 + (l >> 2);
        #pragma unroll
        for (int ni = 0; ni < 4; ni++) {
            int p_ = nw + ni * 8 + (l & 3) * 2;
            tile[p_ * 132 + c_]            = acc[mi][ni][0];
            tile[(p_ + 1) * 132 + c_]      = acc[mi][ni][1];
            tile[p_ * 132 + c_ + 8]        = acc[mi][ni][2];
            tile[(p_ + 1) * 132 + c_ + 8]  = acc[mi][ni][3];
        }
    }
    __syncthreads();

    float* ydst = (MODE == 0) ? g_y1 : g_y2;
    float* gs   = (MODE == 0) ? g_s1 : g_s2;
    float* gss  = (MODE == 0) ? g_ss1 : g_ss2;
    {
        int c = tid & 127;
        int r0 = (tid >> 7) * 64;
        float bi = bias[m0 + c];
        float s = 0.f, s2 = 0.f;
        #pragma unroll 4
        for (int p = 0; p < 64; p++) {
            float v = tile[(r0 + p) * 132 + c] + bi;
            s += v; s2 += v * v;
        }
        atomicAdd(&gs[m0 + c], s);
        atomicAdd(&gss[m0 + c], s2);
    }
    #pragma unroll
    for (int i = 0; i < 16; i++) {
        int t = i * 256 + tid;
        int p = t >> 5, g = t & 31;
        float4 v  = *(const float4*)&tile[p * 132 + g * 4];
        float4 bb = *(const float4*)&bias[m0 + g * 4];
        v.x += bb.x; v.y += bb.y; v.z += bb.z; v.w += bb.w;
        *(float4*)&ydst[(size_t)(p0 + p) * 256 + m0 + g * 4] = v;
    }
}

// ---------------- BN finalize ----------------
__global__ void bnfin_kernel(int which, const float* __restrict__ g,
                             const float* __restrict__ beta) {
    int c = threadIdx.x;
    float s  = which ? g_s2[c]  : g_s1[c];
    float ss = which ? g_ss2[c] : g_ss1[c];
    float mean = s / (float)PTOT;
    float var  = ss / (float)PTOT - mean * mean;
    float A = g[c] * rsqrtf(var + 1e-5f);
    float B = beta[c] - mean * A;
    if (which) { g_bnA2[c] = A; g_bnB2[c] = B; }
    else       { g_bnA1[c] = A; g_bnB1[c] = B; }
}

// ---------------- final: BN2+ReLU + transpose ----------------
__global__ void final_kernel(float* __restrict__ out) {
    __shared__ float tile[32][33];
    int p0 = blockIdx.x * 32, c0 = blockIdx.y * 32;
    int tx = threadIdx.x, ty = threadIdx.y;
    int c = c0 + tx;
    float A = g_bnA2[c], B = g_bnB2[c];
    #pragma unroll
    for (int i = 0; i < 32; i += 8) {
        float v = g_y2[(size_t)(p0 + ty + i) * 256 + c];
        tile[ty + i][tx] = fmaxf(v * A + B, 0.f);
    }
    __syncthreads();
    int b = p0 >> 13;
    int n0 = p0 & (NPTS - 1);
    #pragma unroll
    for (int i = 0; i < 32; i += 8)
        out[(size_t)b * COUT * NPTS + (size_t)(c0 + ty + i) * NPTS + n0 + tx] =
            tile[tx][ty + i];
}

// ---------------------------------------------------------------------------
extern "C" void kernel_launch(void* const* d_in, const int* in_sizes, int n_in,
                              void* d_out, int out_size) {
    const float* pos1  = (const float*)d_in[0];
    const float* pos2  = (const float*)d_in[1];
    const float* feat1 = (const float*)d_in[2];
    const float* feat2 = (const float*)d_in[3];
    const float* W1    = (const float*)d_in[4];
    const float* b1    = (const float*)d_in[5];
    const float* g1    = (const float*)d_in[6];
    const float* be1   = (const float*)d_in[7];
    const float* W2    = (const float*)d_in[8];
    const float* b2    = (const float*)d_in[9];
    const float* g2    = (const float*)d_in[10];
    const float* be2   = (const float*)d_in[11];
    float* out = (float*)d_out;

    cudaFuncSetAttribute(gemm_mma<12, 0>, cudaFuncAttributeMaxDynamicSharedMemorySize, SMEM_DYN);
    cudaFuncSetAttribute(gemm_mma<8, 1>,  cudaFuncAttributeMaxDynamicSharedMemorySize, SMEM_DYN);

    prep_kernel<<<(CMID * CIN + 255) / 256, 256>>>(W1, W2);
    transpose_f2_kernel<<<dim3(SPTS / 32, D2 / 32, BATCH), dim3(32, 8)>>>(feat2);
    knn_kernel<<<dim3(NPTS / 256, BATCH), 256>>>(pos1, pos2);
    interp_kernel<<<PTOT / 8, 256>>>();
    copy_f1_kernel<<<dim3(NPTS / 32, D1 / 32, BATCH), dim3(32, 8)>>>(feat1);
    gemm_mma<12, 0><<<dim3(PTOT / TN, CMID / TM), 256, SMEM_DYN>>>(b1);
    bnfin_kernel<<<1, 256>>>(0, g1, be1);
    convert1_kernel<<<PTOT * CMID / 4 / 256, 256>>>();
    gemm_mma<8, 1><<<dim3(PTOT / TN, COUT / TM), 256, SMEM_DYN>>>(b2);
    bnfin_kernel<<<1, 256>>>(1, g2, be2);
    final_kernel<<<dim3(PTOT / 32, COUT / 32), dim3(32, 8)>>>(out);
}

// round 15
// speedup vs baseline: 1.0889x; 1.0889x over previous
#include <cuda_runtime.h>
#include <cuda_bf16.h>
#include <cstdint>

#define BATCH 4
#define NPTS  8192
#define SPTS  2048
#define D1    128
#define D2    256
#define CIN   384
#define CMID  256
#define COUT  256
#define PTOT  (BATCH*NPTS)   // 32768

#define TM 128
#define TN 128
#define KC 64
#define ROWB 144          // padded SMEM row bytes -> conflict-free ldmatrix
#define OFF_AH 0
#define OFF_AL 18432
#define OFF_BH 36864
#define OFF_BL 55296
#define SMEM_DYN 73728

// ---------------- device scratch ----------------
__device__ float          g_f2t[BATCH*SPTS*D2];
__device__ __nv_bfloat16  g_Fh[(size_t)PTOT*CIN];
__device__ __nv_bfloat16  g_Fl[(size_t)PTOT*CIN];
__device__ float          g_y1[(size_t)PTOT*CMID];
__device__ float          g_y2[(size_t)PTOT*COUT];
__device__ __nv_bfloat16  g_B1h[(size_t)PTOT*CMID];
__device__ __nv_bfloat16  g_B1l[(size_t)PTOT*CMID];
__device__ __nv_bfloat16  g_W1h[CMID*CIN],  g_W1l[CMID*CIN];
__device__ __nv_bfloat16  g_W2h[COUT*CMID], g_W2l[COUT*CMID];
__device__ int            g_idx[PTOT*3];
__device__ float          g_w[PTOT*3];
__device__ float          g_s1[CMID], g_ss1[CMID], g_s2[COUT], g_ss2[COUT];
__device__ float          g_bnA1[CMID], g_bnB1[CMID], g_bnA2[COUT], g_bnB2[COUT];

// ---------------- asm helpers ----------------
static __device__ __forceinline__ uint32_t smem_u32(const void* p) {
    uint32_t a;
    asm("{ .reg .u64 t; cvta.to.shared.u64 t, %1; cvt.u32.u64 %0, t; }" : "=r"(a) : "l"(p));
    return a;
}
static __device__ __forceinline__ void mma16816(float* d, const uint32_t* a,
                                                uint32_t b0, uint32_t b1) {
    asm volatile(
        "mma.sync.aligned.m16n8k16.row.col.f32.bf16.bf16.f32 "
        "{%0,%1,%2,%3}, {%4,%5,%6,%7}, {%8,%9}, {%0,%1,%2,%3};"
        : "+f"(d[0]), "+f"(d[1]), "+f"(d[2]), "+f"(d[3])
        : "r"(a[0]), "r"(a[1]), "r"(a[2]), "r"(a[3]), "r"(b0), "r"(b1));
}
#define LDM4(r0, r1, r2, r3, addr) \
    asm volatile("ldmatrix.sync.aligned.m8n8.x4.shared.b16 {%0,%1,%2,%3}, [%4];" \
        : "=r"(r0), "=r"(r1), "=r"(r2), "=r"(r3) : "r"(addr))
#define CPA(dst, src) \
    asm volatile("cp.async.cg.shared.global [%0], [%1], 16;" :: "r"(dst), "l"(src))
#define CPA_WAIT() do { \
    asm volatile("cp.async.commit_group;"); \
    asm volatile("cp.async.wait_group 0;" ::: "memory"); \
} while (0)

static __device__ __forceinline__ uint32_t pack2(float a, float b) {
    return (uint32_t)__bfloat16_as_ushort(__float2bfloat16(a)) |
           ((uint32_t)__bfloat16_as_ushort(__float2bfloat16(b)) << 16);
}

// ---------------- fused prep: weights->bf16 hi/lo, transpose f2, copy f1 ---
// flat grid: [0,2048) transpose_f2 | [2048,6144) copy_f1 | [6144,6528) prep
__global__ void __launch_bounds__(256) prep_fused_kernel(
    const float* __restrict__ W1, const float* __restrict__ W2,
    const float* __restrict__ f2, const float* __restrict__ f1) {
    int blk = blockIdx.x;
    int tid = threadIdx.x;
    int tx = tid & 31, ty = tid >> 5;   // emulate (32,8)
    if (blk < 2048) {
        // transpose feature2 [B,256,2048] -> fp32 [B,2048,256]
        __shared__ float tile[32][33];
        int b   = blk >> 9;
        int rem = blk & 511;
        int d0  = (rem >> 6) * 32;
        int s0  = (rem & 63) * 32;
        const float* src = f2 + (size_t)b * D2 * SPTS;
        #pragma unroll
        for (int i = 0; i < 32; i += 8)
            tile[ty + i][tx] = src[(size_t)(d0 + ty + i) * SPTS + s0 + tx];
        __syncthreads();
        float* dst = g_f2t + (size_t)b * SPTS * D2;
        #pragma unroll
        for (int i = 0; i < 32; i += 8)
            dst[(size_t)(s0 + ty + i) * D2 + d0 + tx] = tile[tx][ty + i];
    } else if (blk < 6144) {
        // copy feature1 [B,128,8192] -> feat cols [256,384) bf16 hi/lo
        __shared__ float tile[32][33];
        int i2  = blk - 2048;
        int b   = i2 >> 10;
        int rem = i2 & 1023;
        int d0  = (rem >> 8) * 32;
        int n0  = (rem & 255) * 32;
        const float* src = f1 + (size_t)b * D1 * NPTS;
        #pragma unroll
        for (int i = 0; i < 32; i += 8)
            tile[ty + i][tx] = src[(size_t)(d0 + ty + i) * NPTS + n0 + tx];
        __syncthreads();
        #pragma unroll
        for (int i = 0; i < 32; i += 8) {
            float v = tile[tx][ty + i];
            size_t o = (size_t)(b * NPTS + n0 + ty + i) * CIN + D2 + d0 + tx;
            __nv_bfloat16 h = __float2bfloat16(v);
            g_Fh[o] = h;
            g_Fl[o] = __float2bfloat16(v - __bfloat162float(h));
        }
    } else {
        // weights -> bf16 hi/lo + zero BN partial sums
        int i = (blk - 6144) * 256 + tid;
        if (i < CMID * CIN) {
            float w = W1[i];
            __nv_bfloat16 h = __float2bfloat16(w);
            g_W1h[i] = h;
            g_W1l[i] = __float2bfloat16(w - __bfloat162float(h));
        }
        if (i < COUT * CMID) {
            float w = W2[i];
            __nv_bfloat16 h = __float2bfloat16(w);
            g_W2h[i] = h;
            g_W2l[i] = __float2bfloat16(w - __bfloat162float(h));
        }
        if (i < 256) { g_s1[i] = 0.f; g_ss1[i] = 0.f; g_s2[i] = 0.f; g_ss2[i] = 0.f; }
    }
}

// ---------------- 3-NN: float4 candidate layout, 1 LDS.128/iter -----------
__global__ void __launch_bounds__(256) knn_kernel(const float* __restrict__ pos1,
                                                  const float* __restrict__ pos2) {
    __shared__ float4 sp[SPTS];     // 32 KB
    int b = blockIdx.y;
    const float* p2 = pos2 + (size_t)b * 3 * SPTS;
    for (int i = threadIdx.x; i < SPTS; i += blockDim.x) {
        float x = p2[i], y = p2[SPTS + i], z = p2[2 * SPTS + i];
        sp[i] = make_float4(x, y, z, x * x + y * y + z * z);
    }
    __syncthreads();
    int n = blockIdx.x * blockDim.x + threadIdx.x;
    const float* p1 = pos1 + (size_t)b * 3 * NPTS;
    float x = p1[n], y = p1[NPTS + n], z = p1[2 * NPTS + n];
    float sq1 = x * x + y * y + z * z;
    float b0 = 3.4e38f, b1 = 3.4e38f, b2 = 3.4e38f;
    int   i0 = 0, i1 = 0, i2 = 0;
    #pragma unroll 4
    for (int s = 0; s < SPTS; s++) {
        float4 t = sp[s];
        float dot = x * t.x + y * t.y + z * t.z;
        float d   = sq1 - 2.0f * dot + t.w;
        if (d < b2) {
            if (d < b1) {
                if (d < b0) { b2 = b1; i2 = i1; b1 = b0; i1 = i0; b0 = d; i0 = s; }
                else        { b2 = b1; i2 = i1; b1 = d;  i1 = s; }
            } else          { b2 = d;  i2 = s; }
        }
    }
    float w0 = 1.0f / fmaxf(b0, 1e-10f);
    float w1 = 1.0f / fmaxf(b1, 1e-10f);
    float w2 = 1.0f / fmaxf(b2, 1e-10f);
    float ws = w0 + w1 + w2;
    int p = b * NPTS + n;
    g_w[p * 3 + 0] = w0 / ws;  g_w[p * 3 + 1] = w1 / ws;  g_w[p * 3 + 2] = w2 / ws;
    g_idx[p * 3 + 0] = i0;     g_idx[p * 3 + 1] = i1;     g_idx[p * 3 + 2] = i2;
}

// ---------------- interp: warp per point ----------------
__global__ void __launch_bounds__(256) interp_kernel() {
    int p = (blockIdx.x * 256 + threadIdx.x) >> 5;
    int l = threadIdx.x & 31;
    int b = p >> 13;
    int i0 = g_idx[p * 3 + 0], i1 = g_idx[p * 3 + 1], i2 = g_idx[p * 3 + 2];
    float w0 = g_w[p * 3 + 0], w1 = g_w[p * 3 + 1], w2 = g_w[p * 3 + 2];
    const float* r0 = g_f2t + (size_t)(b * SPTS + i0) * D2 + l * 8;
    const float* r1 = g_f2t + (size_t)(b * SPTS + i1) * D2 + l * 8;
    const float* r2 = g_f2t + (size_t)(b * SPTS + i2) * D2 + l * 8;
    float4 a0 = *(const float4*)r0,       a1 = *(const float4*)(r0 + 4);
    float4 c0 = *(const float4*)r1,       c1 = *(const float4*)(r1 + 4);
    float4 e0 = *(const float4*)r2,       e1 = *(const float4*)(r2 + 4);
    float v[8];
    v[0] = w0 * a0.x + w1 * c0.x + w2 * e0.x;
    v[1] = w0 * a0.y + w1 * c0.y + w2 * e0.y;
    v[2] = w0 * a0.z + w1 * c0.z + w2 * e0.z;
    v[3] = w0 * a0.w + w1 * c0.w + w2 * e0.w;
    v[4] = w0 * a1.x + w1 * c1.x + w2 * e1.x;
    v[5] = w0 * a1.y + w1 * c1.y + w2 * e1.y;
    v[6] = w0 * a1.z + w1 * c1.z + w2 * e1.z;
    v[7] = w0 * a1.w + w1 * c1.w + w2 * e1.w;
    uint4 hv, lv;
    float lo[8];
    #pragma unroll
    for (int i = 0; i < 8; i++)
        lo[i] = v[i] - __bfloat162float(__float2bfloat16(v[i]));
    hv.x = pack2(v[0], v[1]); hv.y = pack2(v[2], v[3]);
    hv.z = pack2(v[4], v[5]); hv.w = pack2(v[6], v[7]);
    lv.x = pack2(lo[0], lo[1]); lv.y = pack2(lo[2], lo[3]);
    lv.z = pack2(lo[4], lo[5]); lv.w = pack2(lo[6], lo[7]);
    size_t o = (size_t)p * CIN + l * 8;
    *(uint4*)(g_Fh + o) = hv;
    *(uint4*)(g_Fl + o) = lv;
}

// ---------------- convert y1 -> relu(bn1(y1)) bf16 hi/lo -------------------
__global__ void __launch_bounds__(256) convert1_kernel() {
    size_t i = (size_t)blockIdx.x * 256 + threadIdx.x;
    int c = (int)((i * 4) & 255);
    float4 v  = ((const float4*)g_y1)[i];
    float4 Ac = *(const float4*)&g_bnA1[c];
    float4 Bc = *(const float4*)&g_bnB1[c];
    float x0 = fmaxf(v.x * Ac.x + Bc.x, 0.f);
    float x1 = fmaxf(v.y * Ac.y + Bc.y, 0.f);
    float x2 = fmaxf(v.z * Ac.z + Bc.z, 0.f);
    float x3 = fmaxf(v.w * Ac.w + Bc.w, 0.f);
    uint2 hv, lv;
    hv.x = pack2(x0, x1); hv.y = pack2(x2, x3);
    lv.x = pack2(x0 - __bfloat162float(__float2bfloat16(x0)),
                 x1 - __bfloat162float(__float2bfloat16(x1)));
    lv.y = pack2(x2 - __bfloat162float(__float2bfloat16(x2)),
                 x3 - __bfloat162float(__float2bfloat16(x3)));
    ((uint2*)g_B1h)[i] = hv;
    ((uint2*)g_B1l)[i] = lv;
}

// ---------------- split-bf16 GEMM (ldmatrix + cp.async, KC=64) -------------
// MODE 0: y1 = W1 @ feat^T + b1 (K=384, NC=6)   MODE 1: y2 = W2 @ B1^T + b2 (K=256, NC=4)
template<int NC, int MODE>
__global__ void __launch_bounds__(256, 2) gemm_mma(const float* __restrict__ bias) {
    extern __shared__ __align__(16) char sm[];
    int tid = threadIdx.x;
    int w   = tid >> 5, l = tid & 31;
    int mw  = (w >> 2) * 64;
    int nw  = (w & 3) * 32;
    int m0  = blockIdx.y * TM;
    int p0  = blockIdx.x * TN;
    const int AK = NC * KC;

    const __nv_bfloat16* Ah_src = (MODE == 0) ? g_W1h : g_W2h;
    const __nv_bfloat16* Al_src = (MODE == 0) ? g_W1l : g_W2l;
    const __nv_bfloat16* Bh_src = (MODE == 0) ? g_Fh  : g_B1h;
    const __nv_bfloat16* Bl_src = (MODE == 0) ? g_Fl  : g_B1l;

    uint32_t smb = smem_u32(sm);
    uint32_t aoff = smb + (uint32_t)(mw + (l & 15)) * ROWB + ((l >> 4) * 16);
    uint32_t boff = smb + (uint32_t)(nw + (l & 7) + ((l >> 4) << 3)) * ROWB + (((l >> 3) & 1) * 16);
    int sr = tid >> 3, ssc = tid & 7;
    uint32_t stoff = smb + (uint32_t)sr * ROWB + ssc * 16;

    float acc[4][4][4] = {};

    for (int c = 0; c < NC; ++c) {
        int kc = c * KC;
        if (c) __syncthreads();
        #pragma unroll
        for (int i = 0; i < 4; i++) {
            int r = sr + i * 32;
            uint32_t d = stoff + i * 32 * ROWB;
            const __nv_bfloat16* ga = Ah_src + (size_t)(m0 + r) * AK + kc + ssc * 8;
            const __nv_bfloat16* gl = Al_src + (size_t)(m0 + r) * AK + kc + ssc * 8;
            const __nv_bfloat16* gb = Bh_src + (size_t)(p0 + r) * AK + kc + ssc * 8;
            const __nv_bfloat16* gc = Bl_src + (size_t)(p0 + r) * AK + kc + ssc * 8;
            CPA(d + OFF_AH, ga);
            CPA(d + OFF_AL, gl);
            CPA(d + OFF_BH, gb);
            CPA(d + OFF_BL, gc);
        }
        CPA_WAIT();
        __syncthreads();
        #pragma unroll
        for (int kk = 0; kk < 4; kk++) {
            uint32_t ka = aoff + kk * 32;
            uint32_t kb = boff + kk * 32;
            uint32_t ah[4][4], al[4][4], bh[4][2], bl[4][2];
            #pragma unroll
            for (int mi = 0; mi < 4; mi++) {
                LDM4(ah[mi][0], ah[mi][1], ah[mi][2], ah[mi][3], ka + OFF_AH + mi * (16 * ROWB));
                LDM4(al[mi][0], al[mi][1], al[mi][2], al[mi][3], ka + OFF_AL + mi * (16 * ROWB));
            }
            LDM4(bh[0][0], bh[0][1], bh[1][0], bh[1][1], kb + OFF_BH);
            LDM4(bh[2][0], bh[2][1], bh[3][0], bh[3][1], kb + OFF_BH + 16 * ROWB);
            LDM4(bl[0][0], bl[0][1], bl[1][0], bl[1][1], kb + OFF_BL);
            LDM4(bl[2][0], bl[2][1], bl[3][0], bl[3][1], kb + OFF_BL + 16 * ROWB);
            #pragma unroll
            for (int ni = 0; ni < 4; ni++)
                #pragma unroll
                for (int mi = 0; mi < 4; mi++) {
                    mma16816(acc[mi][ni], ah[mi], bh[ni][0], bh[ni][1]);
                    mma16816(acc[mi][ni], ah[mi], bl[ni][0], bl[ni][1]);
                    mma16816(acc[mi][ni], al[mi], bh[ni][0], bh[ni][1]);
                }
        }
    }

    // --- epilogue: acc -> SMEM tile [128p][132c], stats + coalesced write --
    __syncthreads();
    float* tile = (float*)sm;
    #pragma unroll
    for (int mi = 0; mi < 4; mi++) {
        int c_ = mw + mi * 16 + (l >> 2);
        #pragma unroll
        for (int ni = 0; ni < 4; ni++) {
            int p_ = nw + ni * 8 + (l & 3) * 2;
            tile[p_ * 132 + c_]            = acc[mi][ni][0];
            tile[(p_ + 1) * 132 + c_]      = acc[mi][ni][1];
            tile[p_ * 132 + c_ + 8]        = acc[mi][ni][2];
            tile[(p_ + 1) * 132 + c_ + 8]  = acc[mi][ni][3];
        }
    }
    __syncthreads();

    float* ydst = (MODE == 0) ? g_y1 : g_y2;
    float* gs   = (MODE == 0) ? g_s1 : g_s2;
    float* gss  = (MODE == 0) ? g_ss1 : g_ss2;
    {
        int c = tid & 127;
        int r0 = (tid >> 7) * 64;
        float bi = bias[m0 + c];
        float s = 0.f, s2 = 0.f;
        #pragma unroll 4
        for (int p = 0; p < 64; p++) {
            float v = tile[(r0 + p) * 132 + c] + bi;
            s += v; s2 += v * v;
        }
        atomicAdd(&gs[m0 + c], s);
        atomicAdd(&gss[m0 + c], s2);
    }
    #pragma unroll
    for (int i = 0; i < 16; i++) {
        int t = i * 256 + tid;
        int p = t >> 5, g = t & 31;
        float4 v  = *(const float4*)&tile[p * 132 + g * 4];
        float4 bb = *(const float4*)&bias[m0 + g * 4];
        v.x += bb.x; v.y += bb.y; v.z += bb.z; v.w += bb.w;
        *(float4*)&ydst[(size_t)(p0 + p) * 256 + m0 + g * 4] = v;
    }
}

// ---------------- BN finalize ----------------
__global__ void bnfin_kernel(int which, const float* __restrict__ g,
                             const float* __restrict__ beta) {
    int c = threadIdx.x;
    float s  = which ? g_s2[c]  : g_s1[c];
    float ss = which ? g_ss2[c] : g_ss1[c];
    float mean = s / (float)PTOT;
    float var  = ss / (float)PTOT - mean * mean;
    float A = g[c] * rsqrtf(var + 1e-5f);
    float B = beta[c] - mean * A;
    if (which) { g_bnA2[c] = A; g_bnB2[c] = B; }
    else       { g_bnA1[c] = A; g_bnB1[c] = B; }
}

// ---------------- final: BN2+ReLU + transpose ----------------
__global__ void final_kernel(float* __restrict__ out) {
    __shared__ float tile[32][33];
    int p0 = blockIdx.x * 32, c0 = blockIdx.y * 32;
    int tx = threadIdx.x, ty = threadIdx.y;
    int c = c0 + tx;
    float A = g_bnA2[c], B = g_bnB2[c];
    #pragma unroll
    for (int i = 0; i < 32; i += 8) {
        float v = g_y2[(size_t)(p0 + ty + i) * 256 + c];
        tile[ty + i][tx] = fmaxf(v * A + B, 0.f);
    }
    __syncthreads();
    int b = p0 >> 13;
    int n0 = p0 & (NPTS - 1);
    #pragma unroll
    for (int i = 0; i < 32; i += 8)
        out[(size_t)b * COUT * NPTS + (size_t)(c0 + ty + i) * NPTS + n0 + tx] =
            tile[tx][ty + i];
}

// ---------------------------------------------------------------------------
extern "C" void kernel_launch(void* const* d_in, const int* in_sizes, int n_in,
                              void* d_out, int out_size) {
    const float* pos1  = (const float*)d_in[0];
    const float* pos2  = (const float*)d_in[1];
    const float* feat1 = (const float*)d_in[2];
    const float* feat2 = (const float*)d_in[3];
    const float* W1    = (const float*)d_in[4];
    const float* b1    = (const float*)d_in[5];
    const float* g1    = (const float*)d_in[6];
    const float* be1   = (const float*)d_in[7];
    const float* W2    = (const float*)d_in[8];
    const float* b2    = (const float*)d_in[9];
    const float* g2    = (const float*)d_in[10];
    const float* be2   = (const float*)d_in[11];
    float* out = (float*)d_out;

    cudaFuncSetAttribute(gemm_mma<6, 0>, cudaFuncAttributeMaxDynamicSharedMemorySize, SMEM_DYN);
    cudaFuncSetAttribute(gemm_mma<4, 1>, cudaFuncAttributeMaxDynamicSharedMemorySize, SMEM_DYN);

    // launch order chosen so gemm_mma<6,0> is the 4th launch (ncu capture slot)
    prep_fused_kernel<<<6528, 256>>>(W1, W2, feat2, feat1);
    knn_kernel<<<dim3(NPTS / 256, BATCH), 256>>>(pos1, pos2);
    interp_kernel<<<PTOT / 8, 256>>>();
    gemm_mma<6, 0><<<dim3(PTOT / TN, CMID / TM), 256, SMEM_DYN>>>(b1);
    bnfin_kernel<<<1, 256>>>(0, g1, be1);
    convert1_kernel<<<PTOT * CMID / 4 / 256, 256>>>();
    gemm_mma<4, 1><<<dim3(PTOT / TN, COUT / TM), 256, SMEM_DYN>>>(b2);
    bnfin_kernel<<<1, 256>>>(1, g2, be2);
    final_kernel<<<dim3(PTOT / 32, COUT / 32), dim3(32, 8)>>>(out);
}

// round 16
// speedup vs baseline: 1.1212x; 1.0297x over previous
#include <cuda_runtime.h>
#include <cuda_bf16.h>
#include <cstdint>

#define BATCH 4
#define NPTS  8192
#define SPTS  2048
#define D1    128
#define D2    256
#define CIN   384
#define CMID  256
#define COUT  256
#define PTOT  (BATCH*NPTS)   // 32768

#define TM 128
#define TN 128
#define KC 64
#define ROWB 144            // padded SMEM row bytes -> conflict-free ldmatrix
#define TILE18 18432        // one 128x64 bf16 tile at ROWB=144
#define OFF_AH 0
#define OFF_AL TILE18
#define OFF_B0 (2*TILE18)   // B stage s at OFF_B0 + s*2*TILE18 (BH then BL)
#define SMEM_DYN (6*TILE18) // 110592: A(2) + B stages(2x2)

// ---------------- device scratch ----------------
__device__ float          g_f2t[BATCH*SPTS*D2];
__device__ __nv_bfloat16  g_Fh[(size_t)PTOT*CIN];
__device__ __nv_bfloat16  g_Fl[(size_t)PTOT*CIN];
__device__ float          g_y1[(size_t)PTOT*CMID];
__device__ float          g_y2[(size_t)PTOT*COUT];
__device__ __nv_bfloat16  g_B1h[(size_t)PTOT*CMID];
__device__ __nv_bfloat16  g_B1l[(size_t)PTOT*CMID];
__device__ __nv_bfloat16  g_W1h[CMID*CIN],  g_W1l[CMID*CIN];
__device__ __nv_bfloat16  g_W2h[COUT*CMID], g_W2l[COUT*CMID];
__device__ int            g_idx[PTOT*3];
__device__ float          g_w[PTOT*3];
__device__ float          g_s1[CMID], g_ss1[CMID], g_s2[COUT], g_ss2[COUT];
__device__ float          g_bnA1[CMID], g_bnB1[CMID], g_bnA2[COUT], g_bnB2[COUT];

// ---------------- asm helpers ----------------
static __device__ __forceinline__ uint32_t smem_u32(const void* p) {
    uint32_t a;
    asm("{ .reg .u64 t; cvta.to.shared.u64 t, %1; cvt.u32.u64 %0, t; }" : "=r"(a) : "l"(p));
    return a;
}
static __device__ __forceinline__ void mma16816(float* d, const uint32_t* a,
                                                uint32_t b0, uint32_t b1) {
    asm volatile(
        "mma.sync.aligned.m16n8k16.row.col.f32.bf16.bf16.f32 "
        "{%0,%1,%2,%3}, {%4,%5,%6,%7}, {%8,%9}, {%0,%1,%2,%3};"
        : "+f"(d[0]), "+f"(d[1]), "+f"(d[2]), "+f"(d[3])
        : "r"(a[0]), "r"(a[1]), "r"(a[2]), "r"(a[3]), "r"(b0), "r"(b1));
}
#define LDM4(r0, r1, r2, r3, addr) \
    asm volatile("ldmatrix.sync.aligned.m8n8.x4.shared.b16 {%0,%1,%2,%3}, [%4];" \
        : "=r"(r0), "=r"(r1), "=r"(r2), "=r"(r3) : "r"(addr))
#define CPA(dst, src) \
    asm volatile("cp.async.cg.shared.global [%0], [%1], 16;" :: "r"(dst), "l"(src))
#define CPA_COMMIT() asm volatile("cp.async.commit_group;")
#define CPA_WAIT1()  asm volatile("cp.async.wait_group 1;" ::: "memory")
#define CPA_WAIT0()  asm volatile("cp.async.wait_group 0;" ::: "memory")

static __device__ __forceinline__ uint32_t pack2(float a, float b) {
    return (uint32_t)__bfloat16_as_ushort(__float2bfloat16(a)) |
           ((uint32_t)__bfloat16_as_ushort(__float2bfloat16(b)) << 16);
}

// ---------------- fused prep: weights->bf16 hi/lo, transpose f2, copy f1 ---
__global__ void __launch_bounds__(256) prep_fused_kernel(
    const float* __restrict__ W1, const float* __restrict__ W2,
    const float* __restrict__ f2, const float* __restrict__ f1) {
    int blk = blockIdx.x;
    int tid = threadIdx.x;
    int tx = tid & 31, ty = tid >> 5;
    if (blk < 2048) {
        __shared__ float tile[32][33];
        int b   = blk >> 9;
        int rem = blk & 511;
        int d0  = (rem >> 6) * 32;
        int s0  = (rem & 63) * 32;
        const float* src = f2 + (size_t)b * D2 * SPTS;
        #pragma unroll
        for (int i = 0; i < 32; i += 8)
            tile[ty + i][tx] = src[(size_t)(d0 + ty + i) * SPTS + s0 + tx];
        __syncthreads();
        float* dst = g_f2t + (size_t)b * SPTS * D2;
        #pragma unroll
        for (int i = 0; i < 32; i += 8)
            dst[(size_t)(s0 + ty + i) * D2 + d0 + tx] = tile[tx][ty + i];
    } else if (blk < 6144) {
        __shared__ float tile[32][33];
        int i2  = blk - 2048;
        int b   = i2 >> 10;
        int rem = i2 & 1023;
        int d0  = (rem >> 8) * 32;
        int n0  = (rem & 255) * 32;
        const float* src = f1 + (size_t)b * D1 * NPTS;
        #pragma unroll
        for (int i = 0; i < 32; i += 8)
            tile[ty + i][tx] = src[(size_t)(d0 + ty + i) * NPTS + n0 + tx];
        __syncthreads();
        #pragma unroll
        for (int i = 0; i < 32; i += 8) {
            float v = tile[tx][ty + i];
            size_t o = (size_t)(b * NPTS + n0 + ty + i) * CIN + D2 + d0 + tx;
            __nv_bfloat16 h = __float2bfloat16(v);
            g_Fh[o] = h;
            g_Fl[o] = __float2bfloat16(v - __bfloat162float(h));
        }
    } else {
        int i = (blk - 6144) * 256 + tid;
        if (i < CMID * CIN) {
            float w = W1[i];
            __nv_bfloat16 h = __float2bfloat16(w);
            g_W1h[i] = h;
            g_W1l[i] = __float2bfloat16(w - __bfloat162float(h));
        }
        if (i < COUT * CMID) {
            float w = W2[i];
            __nv_bfloat16 h = __float2bfloat16(w);
            g_W2h[i] = h;
            g_W2l[i] = __float2bfloat16(w - __bfloat162float(h));
        }
        if (i < 256) { g_s1[i] = 0.f; g_ss1[i] = 0.f; g_s2[i] = 0.f; g_ss2[i] = 0.f; }
    }
}

// ---------------- 3-NN ----------------
__global__ void __launch_bounds__(256) knn_kernel(const float* __restrict__ pos1,
                                                  const float* __restrict__ pos2) {
    __shared__ float4 sp[SPTS];
    int b = blockIdx.y;
    const float* p2 = pos2 + (size_t)b * 3 * SPTS;
    for (int i = threadIdx.x; i < SPTS; i += blockDim.x) {
        float x = p2[i], y = p2[SPTS + i], z = p2[2 * SPTS + i];
        sp[i] = make_float4(x, y, z, x * x + y * y + z * z);
    }
    __syncthreads();
    int n = blockIdx.x * blockDim.x + threadIdx.x;
    const float* p1 = pos1 + (size_t)b * 3 * NPTS;
    float x = p1[n], y = p1[NPTS + n], z = p1[2 * NPTS + n];
    float sq1 = x * x + y * y + z * z;
    float b0 = 3.4e38f, b1 = 3.4e38f, b2 = 3.4e38f;
    int   i0 = 0, i1 = 0, i2 = 0;
    #pragma unroll 4
    for (int s = 0; s < SPTS; s++) {
        float4 t = sp[s];
        float dot = x * t.x + y * t.y + z * t.z;
        float d   = sq1 - 2.0f * dot + t.w;
        if (d < b2) {
            if (d < b1) {
                if (d < b0) { b2 = b1; i2 = i1; b1 = b0; i1 = i0; b0 = d; i0 = s; }
                else        { b2 = b1; i2 = i1; b1 = d;  i1 = s; }
            } else          { b2 = d;  i2 = s; }
        }
    }
    float w0 = 1.0f / fmaxf(b0, 1e-10f);
    float w1 = 1.0f / fmaxf(b1, 1e-10f);
    float w2 = 1.0f / fmaxf(b2, 1e-10f);
    float ws = w0 + w1 + w2;
    int p = b * NPTS + n;
    g_w[p * 3 + 0] = w0 / ws;  g_w[p * 3 + 1] = w1 / ws;  g_w[p * 3 + 2] = w2 / ws;
    g_idx[p * 3 + 0] = i0;     g_idx[p * 3 + 1] = i1;     g_idx[p * 3 + 2] = i2;
}

// ---------------- interp: warp per point ----------------
__global__ void __launch_bounds__(256) interp_kernel() {
    int p = (blockIdx.x * 256 + threadIdx.x) >> 5;
    int l = threadIdx.x & 31;
    int b = p >> 13;
    int i0 = g_idx[p * 3 + 0], i1 = g_idx[p * 3 + 1], i2 = g_idx[p * 3 + 2];
    float w0 = g_w[p * 3 + 0], w1 = g_w[p * 3 + 1], w2 = g_w[p * 3 + 2];
    const float* r0 = g_f2t + (size_t)(b * SPTS + i0) * D2 + l * 8;
    const float* r1 = g_f2t + (size_t)(b * SPTS + i1) * D2 + l * 8;
    const float* r2 = g_f2t + (size_t)(b * SPTS + i2) * D2 + l * 8;
    float4 a0 = *(const float4*)r0,       a1 = *(const float4*)(r0 + 4);
    float4 c0 = *(const float4*)r1,       c1 = *(const float4*)(r1 + 4);
    float4 e0 = *(const float4*)r2,       e1 = *(const float4*)(r2 + 4);
    float v[8];
    v[0] = w0 * a0.x + w1 * c0.x + w2 * e0.x;
    v[1] = w0 * a0.y + w1 * c0.y + w2 * e0.y;
    v[2] = w0 * a0.z + w1 * c0.z + w2 * e0.z;
    v[3] = w0 * a0.w + w1 * c0.w + w2 * e0.w;
    v[4] = w0 * a1.x + w1 * c1.x + w2 * e1.x;
    v[5] = w0 * a1.y + w1 * c1.y + w2 * e1.y;
    v[6] = w0 * a1.z + w1 * c1.z + w2 * e1.z;
    v[7] = w0 * a1.w + w1 * c1.w + w2 * e1.w;
    uint4 hv, lv;
    float lo[8];
    #pragma unroll
    for (int i = 0; i < 8; i++)
        lo[i] = v[i] - __bfloat162float(__float2bfloat16(v[i]));
    hv.x = pack2(v[0], v[1]); hv.y = pack2(v[2], v[3]);
    hv.z = pack2(v[4], v[5]); hv.w = pack2(v[6], v[7]);
    lv.x = pack2(lo[0], lo[1]); lv.y = pack2(lo[2], lo[3]);
    lv.z = pack2(lo[4], lo[5]); lv.w = pack2(lo[6], lo[7]);
    size_t o = (size_t)p * CIN + l * 8;
    *(uint4*)(g_Fh + o) = hv;
    *(uint4*)(g_Fl + o) = lv;
}

// ---------------- convert y1 -> relu(bn1(y1)) bf16 hi/lo -------------------
__global__ void __launch_bounds__(256) convert1_kernel() {
    size_t i = (size_t)blockIdx.x * 256 + threadIdx.x;
    int c = (int)((i * 4) & 255);
    float4 v  = ((const float4*)g_y1)[i];
    float4 Ac = *(const float4*)&g_bnA1[c];
    float4 Bc = *(const float4*)&g_bnB1[c];
    float x0 = fmaxf(v.x * Ac.x + Bc.x, 0.f);
    float x1 = fmaxf(v.y * Ac.y + Bc.y, 0.f);
    float x2 = fmaxf(v.z * Ac.z + Bc.z, 0.f);
    float x3 = fmaxf(v.w * Ac.w + Bc.w, 0.f);
    uint2 hv, lv;
    hv.x = pack2(x0, x1); hv.y = pack2(x2, x3);
    lv.x = pack2(x0 - __bfloat162float(__float2bfloat16(x0)),
                 x1 - __bfloat162float(__float2bfloat16(x1)));
    lv.y = pack2(x2 - __bfloat162float(__float2bfloat16(x2)),
                 x3 - __bfloat162float(__float2bfloat16(x3)));
    ((uint2*)g_B1h)[i] = hv;
    ((uint2*)g_B1l)[i] = lv;
}

// -------- split-bf16 GEMM: B double-buffered (DRAM), A single (L2-hot) -----
// MODE 0: y1 = W1 @ feat^T + b1 (K=384, NC=6)   MODE 1: y2 = W2 @ B1^T + b2 (K=256, NC=4)
template<int NC, int MODE>
__global__ void __launch_bounds__(256, 2) gemm_mma(const float* __restrict__ bias) {
    extern __shared__ __align__(16) char sm[];
    int tid = threadIdx.x;
    int w   = tid >> 5, l = tid & 31;
    int mw  = (w >> 2) * 64;
    int nw  = (w & 3) * 32;
    int m0  = blockIdx.y * TM;
    int p0  = blockIdx.x * TN;
    const int AK = NC * KC;

    const __nv_bfloat16* Ah_src = (MODE == 0) ? g_W1h : g_W2h;
    const __nv_bfloat16* Al_src = (MODE == 0) ? g_W1l : g_W2l;
    const __nv_bfloat16* Bh_src = (MODE == 0) ? g_Fh  : g_B1h;
    const __nv_bfloat16* Bl_src = (MODE == 0) ? g_Fl  : g_B1l;

    uint32_t smb = smem_u32(sm);
    uint32_t aoff = smb + (uint32_t)(mw + (l & 15)) * ROWB + ((l >> 4) * 16);
    uint32_t boff = smb + (uint32_t)(nw + (l & 7) + ((l >> 4) << 3)) * ROWB + (((l >> 3) & 1) * 16);
    int sr = tid >> 3, ssc = tid & 7;
    uint32_t stoff = (uint32_t)sr * ROWB + ssc * 16;

    float acc[4][4][4] = {};

    // prologue: B chunk 0 -> stage 0
    {
        uint32_t d = smb + OFF_B0 + stoff;
        #pragma unroll
        for (int i = 0; i < 4; i++) {
            int r = sr + i * 32;
            const __nv_bfloat16* gb = Bh_src + (size_t)(p0 + r) * AK + ssc * 8;
            const __nv_bfloat16* gc = Bl_src + (size_t)(p0 + r) * AK + ssc * 8;
            CPA(d + i * 32 * ROWB, gb);
            CPA(d + i * 32 * ROWB + TILE18, gc);
        }
        CPA_COMMIT();
    }

    for (int c = 0; c < NC; ++c) {
        int kc = c * KC;
        // A chunk c (L2-hot) into the single A buffer
        #pragma unroll
        for (int i = 0; i < 4; i++) {
            int r = sr + i * 32;
            uint32_t d = smb + stoff + i * 32 * ROWB;
            const __nv_bfloat16* ga = Ah_src + (size_t)(m0 + r) * AK + kc + ssc * 8;
            const __nv_bfloat16* gl = Al_src + (size_t)(m0 + r) * AK + kc + ssc * 8;
            CPA(d + OFF_AH, ga);
            CPA(d + OFF_AL, gl);
        }
        CPA_COMMIT();
        if (c + 1 < NC) {
            // prefetch B chunk c+1 into the other stage
            uint32_t d = smb + OFF_B0 + ((c + 1) & 1) * (2 * TILE18) + stoff;
            #pragma unroll
            for (int i = 0; i < 4; i++) {
                int r = sr + i * 32;
                const __nv_bfloat16* gb = Bh_src + (size_t)(p0 + r) * AK + kc + KC + ssc * 8;
                const __nv_bfloat16* gc = Bl_src + (size_t)(p0 + r) * AK + kc + KC + ssc * 8;
                CPA(d + i * 32 * ROWB, gb);
                CPA(d + i * 32 * ROWB + TILE18, gc);
            }
            CPA_COMMIT();
            CPA_WAIT1();          // A_c and B_c complete; B_{c+1} in flight
        } else {
            CPA_WAIT0();
        }
        __syncthreads();
        uint32_t bbase = OFF_B0 + (c & 1) * (2 * TILE18);
        #pragma unroll
        for (int kk = 0; kk < 4; kk++) {
            uint32_t ka = aoff + kk * 32;
            uint32_t kb = boff + bbase + kk * 32;
            uint32_t ah[4][4], al[4][4], bh[4][2], bl[4][2];
            #pragma unroll
            for (int mi = 0; mi < 4; mi++) {
                LDM4(ah[mi][0], ah[mi][1], ah[mi][2], ah[mi][3], ka + OFF_AH + mi * (16 * ROWB));
                LDM4(al[mi][0], al[mi][1], al[mi][2], al[mi][3], ka + OFF_AL + mi * (16 * ROWB));
            }
            LDM4(bh[0][0], bh[0][1], bh[1][0], bh[1][1], kb);
            LDM4(bh[2][0], bh[2][1], bh[3][0], bh[3][1], kb + 16 * ROWB);
            LDM4(bl[0][0], bl[0][1], bl[1][0], bl[1][1], kb + TILE18);
            LDM4(bl[2][0], bl[2][1], bl[3][0], bl[3][1], kb + TILE18 + 16 * ROWB);
            #pragma unroll
            for (int ni = 0; ni < 4; ni++)
                #pragma unroll
                for (int mi = 0; mi < 4; mi++) {
                    mma16816(acc[mi][ni], ah[mi], bh[ni][0], bh[ni][1]);
                    mma16816(acc[mi][ni], ah[mi], bl[ni][0], bl[ni][1]);
                    mma16816(acc[mi][ni], al[mi], bh[ni][0], bh[ni][1]);
                }
        }
        __syncthreads();   // compute done before A buf / B stage reuse
    }

    // --- epilogue: acc -> SMEM tile [128p][132c], stats + coalesced write --
    float* tile = (float*)sm;
    #pragma unroll
    for (int mi = 0; mi < 4; mi++) {
        int c_ = mw + mi * 16 + (l >> 2);
        #pragma unroll
        for (int ni = 0; ni < 4; ni++) {
            int p_ = nw + ni * 8 + (l & 3) * 2;
            tile[p_ * 132 + c_]            = acc[mi][ni][0];
            tile[(p_ + 1) * 132 + c_]      = acc[mi][ni][1];
            tile[p_ * 132 + c_ + 8]        = acc[mi][ni][2];
            tile[(p_ + 1) * 132 + c_ + 8]  = acc[mi][ni][3];
        }
    }
    __syncthreads();

    float* ydst = (MODE == 0) ? g_y1 : g_y2;
    float* gs   = (MODE == 0) ? g_s1 : g_s2;
    float* gss  = (MODE == 0) ? g_ss1 : g_ss2;
    {
        int c = tid & 127;
        int r0 = (tid >> 7) * 64;
        float bi = bias[m0 + c];
        float s = 0.f, s2 = 0.f;
        #pragma unroll 4
        for (int p = 0; p < 64; p++) {
            float v = tile[(r0 + p) * 132 + c] + bi;
            s += v; s2 += v * v;
        }
        atomicAdd(&gs[m0 + c], s);
        atomicAdd(&gss[m0 + c], s2);
    }
    #pragma unroll
    for (int i = 0; i < 16; i++) {
        int t = i * 256 + tid;
        int p = t >> 5, g = t & 31;
        float4 v  = *(const float4*)&tile[p * 132 + g * 4];
        float4 bb = *(const float4*)&bias[m0 + g * 4];
        v.x += bb.x; v.y += bb.y; v.z += bb.z; v.w += bb.w;
        *(float4*)&ydst[(size_t)(p0 + p) * 256 + m0 + g * 4] = v;
    }
}

// ---------------- BN finalize ----------------
__global__ void bnfin_kernel(int which, const float* __restrict__ g,
                             const float* __restrict__ beta) {
    int c = threadIdx.x;
    float s  = which ? g_s2[c]  : g_s1[c];
    float ss = which ? g_ss2[c] : g_ss1[c];
    float mean = s / (float)PTOT;
    float var  = ss / (float)PTOT - mean * mean;
    float A = g[c] * rsqrtf(var + 1e-5f);
    float B = beta[c] - mean * A;
    if (which) { g_bnA2[c] = A; g_bnB2[c] = B; }
    else       { g_bnA1[c] = A; g_bnB1[c] = B; }
}

// ---------------- final: BN2+ReLU + transpose ----------------
__global__ void final_kernel(float* __restrict__ out) {
    __shared__ float tile[32][33];
    int p0 = blockIdx.x * 32, c0 = blockIdx.y * 32;
    int tx = threadIdx.x, ty = threadIdx.y;
    int c = c0 + tx;
    float A = g_bnA2[c], B = g_bnB2[c];
    #pragma unroll
    for (int i = 0; i < 32; i += 8) {
        float v = g_y2[(size_t)(p0 + ty + i) * 256 + c];
        tile[ty + i][tx] = fmaxf(v * A + B, 0.f);
    }
    __syncthreads();
    int b = p0 >> 13;
    int n0 = p0 & (NPTS - 1);
    #pragma unroll
    for (int i = 0; i < 32; i += 8)
        out[(size_t)b * COUT * NPTS + (size_t)(c0 + ty + i) * NPTS + n0 + tx] =
            tile[tx][ty + i];
}

// ---------------------------------------------------------------------------
extern "C" void kernel_launch(void* const* d_in, const int* in_sizes, int n_in,
                              void* d_out, int out_size) {
    const float* pos1  = (const float*)d_in[0];
    const float* pos2  = (const float*)d_in[1];
    const float* feat1 = (const float*)d_in[2];
    const float* feat2 = (const float*)d_in[3];
    const float* W1    = (const float*)d_in[4];
    const float* b1    = (const float*)d_in[5];
    const float* g1    = (const float*)d_in[6];
    const float* be1   = (const float*)d_in[7];
    const float* W2    = (const float*)d_in[8];
    const float* b2    = (const float*)d_in[9];
    const float* g2    = (const float*)d_in[10];
    const float* be2   = (const float*)d_in[11];
    float* out = (float*)d_out;

    cudaFuncSetAttribute(gemm_mma<6, 0>, cudaFuncAttributeMaxDynamicSharedMemorySize, SMEM_DYN);
    cudaFuncSetAttribute(gemm_mma<4, 1>, cudaFuncAttributeMaxDynamicSharedMemorySize, SMEM_DYN);

    // launch order keeps gemm_mma<6,0> as the 4th launch (ncu capture slot)
    prep_fused_kernel<<<6528, 256>>>(W1, W2, feat2, feat1);
    knn_kernel<<<dim3(NPTS / 256, BATCH), 256>>>(pos1, pos2);
    interp_kernel<<<PTOT / 8, 256>>>();
    gemm_mma<6, 0><<<dim3(PTOT / TN, CMID / TM), 256, SMEM_DYN>>>(b1);
    bnfin_kernel<<<1, 256>>>(0, g1, be1);
    convert1_kernel<<<PTOT * CMID / 4 / 256, 256>>>();
    gemm_mma<4, 1><<<dim3(PTOT / TN, COUT / TM), 256, SMEM_DYN>>>(b2);
    bnfin_kernel<<<1, 256>>>(1, g2, be2);
    final_kernel<<<dim3(PTOT / 32, COUT / 32), dim3(32, 8)>>>(out);
}